// round 10
// baseline (speedup 1.0000x reference)
#include <cuda_runtime.h>
#include <cuda_fp16.h>
#include <cstdint>
#include <math.h>

typedef unsigned long long ull;

#define FMA2(acc, a, b) asm("fma.rn.f32x2 %0, %1, %2, %0;" : "+l"(acc) : "l"(a), "l"(b))
#define PACK2(d, s)     asm("mov.b64 %0, {%1, %1};" : "=l"(d) : "f"(s))
#define UNPACK2(lo, hi, s) asm("mov.b64 {%0, %1}, %2;" : "=f"(lo), "=f"(hi) : "l"(s))
#define CP_ASYNC16(dst, src) \
    asm volatile("cp.async.cg.shared.global [%0], [%1], 16;" :: "r"(dst), "l"(src) : "memory")
#define CP_COMMIT()  asm volatile("cp.async.commit_group;" ::: "memory")
#define CP_WAIT0()   asm volatile("cp.async.wait_group 0;" ::: "memory")

constexpr int N    = 8192;
constexpr int FIN  = 512;
constexpr int FOUT = 128;
constexpr int NQ   = 512;    // k16 chunks
constexpr int NG3  = 170;    // groups of 3 chunks (2 tensor + 1 cuda); tail = chunks 510,511

__device__ float g_h[N * FOUT];
__device__ uint2 g_hTb[NQ * 16 * 4 * 8];     // fp16 B fragments of h^T (2MB, L2-resident)
__device__ float g_E1[N], g_F1[N], g_E2[N], g_F2[N];

__device__ __forceinline__ uint32_t smem_u32(const void* p) {
    return (uint32_t)__cvta_generic_to_shared(p);
}
__device__ __forceinline__ uint32_t pack_h2(float lo, float hi) {
    uint32_t r;
    asm("cvt.rn.f16x2.f32 %0, %1, %2;" : "=r"(r) : "f"(hi), "f"(lo));
    return r;
}
__device__ __forceinline__ float2 h2f2(uint32_t u) {
    __half2 h = *reinterpret_cast<const __half2*>(&u);
    return __half22float2(h);
}

// m16n8k16 fp16 warp MMA, fp32 accumulate
__device__ __forceinline__ void mma16(float* c, uint32_t a0, uint32_t a1, uint32_t a2,
                                      uint32_t a3, uint32_t b0, uint32_t b1) {
    asm volatile(
        "mma.sync.aligned.m16n8k16.row.col.f32.f16.f16.f32 "
        "{%0,%1,%2,%3}, {%4,%5,%6,%7}, {%8,%9}, {%0,%1,%2,%3};"
        : "+f"(c[0]), "+f"(c[1]), "+f"(c[2]), "+f"(c[3])
        : "r"(a0), "r"(a1), "r"(a2), "r"(a3), "r"(b0), "r"(b1));
}

__device__ __forceinline__ float elu_f(float v) { return v > 0.f ? v : expm1f(v); }

// ---------------------------------------------------------------------------
// Kernel A: h = X @ W (fp32 FFMA2), BM=64. Emits g_h and fp16 B-fragment hT.
// ---------------------------------------------------------------------------
__global__ void __launch_bounds__(256) k_gemm_hw(const float* __restrict__ X,
                                                 const float* __restrict__ W) {
    __shared__ float sX[64][32];
    __shared__ float sB[32][FOUT];
    const int t = threadIdx.x;
    const int tx = t & 31, ty = t >> 5;
    const int m0 = blockIdx.x * 64;
    const int xr = t >> 2, xc0 = (t & 3) * 8;
    const int wr = t >> 3, wc0 = (t & 7) * 16;

    ull acc[8][2] = {};
    for (int kc = 0; kc < FIN / 32; ++kc) {
        const int k0 = kc * 32;
        __syncthreads();
        {
            float4*       dx = reinterpret_cast<float4*>(&sX[xr][xc0]);
            const float4* sx = reinterpret_cast<const float4*>(X + (size_t)(m0 + xr) * FIN + k0 + xc0);
            dx[0] = sx[0]; dx[1] = sx[1];
            float4*       dw = reinterpret_cast<float4*>(&sB[wr][wc0]);
            const float4* sw = reinterpret_cast<const float4*>(W + (size_t)(k0 + wr) * FOUT + wc0);
            dw[0] = sw[0]; dw[1] = sw[1]; dw[2] = sw[2]; dw[3] = sw[3];
        }
        __syncthreads();
        #pragma unroll 8
        for (int kk = 0; kk < 32; ++kk) {
            ulonglong2 b2 = *reinterpret_cast<const ulonglong2*>(&sB[kk][tx << 2]);
            #pragma unroll
            for (int k = 0; k < 8; ++k) {
                ull ap; PACK2(ap, sX[ty + 8 * k][kk]);
                FMA2(acc[k][0], ap, b2.x);
                FMA2(acc[k][1], ap, b2.y);
            }
        }
    }
    __half* hTb = reinterpret_cast<__half*>(g_hTb);
    #pragma unroll
    for (int k = 0; k < 8; ++k) {
        const int r = m0 + ty + 8 * k;
        float4 o;
        UNPACK2(o.x, o.y, acc[k][0]);
        UNPACK2(o.z, o.w, acc[k][1]);
        reinterpret_cast<float4*>(g_h + (size_t)r * FOUT)[tx] = o;
        const int q  = r >> 4;
        const int lc = (r >> 2) & 3;
        const int p  = r & 3;
        const float v[4] = {o.x, o.y, o.z, o.w};
        #pragma unroll
        for (int c = 0; c < 4; ++c) {
            const int f = tx * 4 + c;
            const int idx = (((q * 16 + (f >> 3)) * 4 + lc) * 8 + (f & 7)) * 4 + p;
            hTb[idx] = __float2half_rn(v[c]);
        }
    }
}

// ---------------------------------------------------------------------------
// Kernel B: E/F exp vectors
// ---------------------------------------------------------------------------
__global__ void __launch_bounds__(128) k_scores(const float* __restrict__ a) {
    const int i = blockIdx.x;
    const int t = threadIdx.x;
    const float hv = g_h[(size_t)i * FOUT + t];
    float p1 = hv * __ldg(&a[t]);
    float p2 = hv * __ldg(&a[FOUT + t]);
    #pragma unroll
    for (int off = 16; off; off >>= 1) {
        p1 += __shfl_xor_sync(0xffffffffu, p1, off);
        p2 += __shfl_xor_sync(0xffffffffu, p2, off);
    }
    __shared__ float r1[4], r2[4];
    const int w = t >> 5;
    if ((t & 31) == 0) { r1[w] = p1; r2[w] = p2; }
    __syncthreads();
    if (t == 0) {
        const float s1 = r1[0] + r1[1] + r1[2] + r1[3];
        const float s2 = r2[0] + r2[1] + r2[2] + r2[3];
        g_E1[i] = __expf(s1);  g_F1[i] = __expf(0.2f * s1);
        g_E2[i] = __expf(s2);  g_F2[i] = __expf(0.2f * s2);
    }
}

// ---------------------------------------------------------------------------
// Kernel C: hybrid tensor+CUDA aggregation with SEPARATE accumulators.
// Groups of 3 chunks: 2 x fp16 mma.sync (acc) + 1 x fp32 FMA2 (accC).
// No register dependency between the two streams -> tensor pipe and fma pipe
// overlap; merged in the epilogue. den off the HMMA queue (warps 1,6).
// ---------------------------------------------------------------------------
__global__ void __launch_bounds__(256, 1) k_agg(const int* __restrict__ adj,
                                                float* __restrict__ out) {
    extern __shared__ float smem[];
    float* sEF = smem;                      // [0,8192)=E2, [8192,16384)=F2  (64KB)
    float* sH  = smem + 2 * N;              // 2 x 2048 floats (h chunk double buffer, 16KB)
    __shared__ uint32_t sBal[2][32];        // adj ballot words, double-buffered
    __shared__ float sDen[64];

    const int t = threadIdx.x;
    const int lane = t & 31, wid = t >> 5;
    const int mw = wid >> 2, nw = wid & 3;
    const int lr = lane >> 2, lc = lane & 3;
    const int i0 = blockIdx.x * 64;
    const bool do_den = (wid == 1) || (wid == 6);

    // stage E2/F2 tables
    {
        const float4* e4 = reinterpret_cast<const float4*>(g_E2);
        const float4* f4 = reinterpret_cast<const float4*>(g_F2);
        float4* s4 = reinterpret_cast<float4*>(sEF);
        for (int k = t; k < N / 4; k += 256) {
            s4[k]         = e4[k];
            s4[N / 4 + k] = f4[k];
        }
    }

    const int4* adj4 = reinterpret_cast<const int4*>(adj);

    // per-lane row data
    float e1[4], f1[4];
    const int4* arow[4];
    #pragma unroll
    for (int k = 0; k < 4; ++k) {
        const int row = i0 + mw * 32 + lr + 8 * k;
        e1[k] = g_E1[row];
        f1[k] = g_F1[row];
        arow[k] = adj4 + (size_t)row * (N / 4) + lc;
    }

    // cuda-chunk staging mappings
    const int crow = t >> 2, cseg = t & 3;                    // adj: thread -> (row, 16B seg)
    const int4* csrc_base = adj4 + (size_t)(i0 + crow) * (N / 4) + cseg;
    const uint32_t hdst0 = smem_u32(sH) + (uint32_t)t * 32;   // h: thread -> 32B

    // prologue: h stage (buffer 0, for group 0's cuda chunk qc=2) + adj regs
    int4 ac4 = __ldg(csrc_base + 2 * 4);
    CP_ASYNC16(hdst0,      (const char*)(g_h + 2 * 2048) + t * 32);
    CP_ASYNC16(hdst0 + 16, (const char*)(g_h + 2 * 2048) + t * 32 + 16);
    CP_COMMIT();

    // tensor prefetch for chunk 0
    int4 a4n[4];
    uint2 b2n[4];
    #pragma unroll
    for (int k = 0; k < 4; ++k) a4n[k] = __ldg(arow[k]);
    #pragma unroll
    for (int nt = 0; nt < 4; ++nt)
        b2n[nt] = __ldg(&g_hTb[((nw * 4 + nt) * 4 + lc) * 8 + lr]);

    float acc[2][4][4];                 // tensor accumulators (C-fragment layout)
    ull   accC[2][4][2] = {};           // cuda accumulators, packed f32x2 pairs
    #pragma unroll
    for (int mt = 0; mt < 2; ++mt)
        #pragma unroll
        for (int nt = 0; nt < 4; ++nt)
            #pragma unroll
            for (int r = 0; r < 4; ++r) acc[mt][nt][r] = 0.f;
    float dpT[4] = {0.f, 0.f, 0.f, 0.f};
    float dpC[4] = {0.f, 0.f, 0.f, 0.f};

    const float4* sE4 = reinterpret_cast<const float4*>(sEF);
    const float4* sF4 = reinterpret_cast<const float4*>(sEF + N);

    // tensor-chunk body (weights -> fp16 A frags -> mma into acc)
    auto tensor_chunk = [&](int q, int nq) {
        int4 a4[4];
        uint2 b2[4];
        #pragma unroll
        for (int k = 0; k < 4; ++k) a4[k] = a4n[k];
        #pragma unroll
        for (int nt = 0; nt < 4; ++nt) b2[nt] = b2n[nt];
        if (nq < NQ) {
            #pragma unroll
            for (int k = 0; k < 4; ++k) a4n[k] = __ldg(arow[k] + nq * 4);
            #pragma unroll
            for (int nt = 0; nt < 4; ++nt)
                b2n[nt] = __ldg(&g_hTb[((nq * 16 + nw * 4 + nt) * 4 + lc) * 8 + lr]);
        }
        const float4 e4 = sE4[q * 4 + lc];
        const float4 f4 = sF4[q * 4 + lc];

        float w[4][4];
        #pragma unroll
        for (int k = 0; k < 4; ++k) {
            const float ek = e1[k], fk = f1[k];
            w[k][0] = a4[k].x ? fmaxf(ek * e4.x, fk * f4.x) : 0.f;
            w[k][1] = a4[k].y ? fmaxf(ek * e4.y, fk * f4.y) : 0.f;
            w[k][2] = a4[k].z ? fmaxf(ek * e4.z, fk * f4.z) : 0.f;
            w[k][3] = a4[k].w ? fmaxf(ek * e4.w, fk * f4.w) : 0.f;
        }
        #pragma unroll
        for (int mt = 0; mt < 2; ++mt) {
            const uint32_t af0 = pack_h2(w[2 * mt][0],     w[2 * mt][1]);
            const uint32_t af1 = pack_h2(w[2 * mt + 1][0], w[2 * mt + 1][1]);
            const uint32_t af2 = pack_h2(w[2 * mt][2],     w[2 * mt][3]);
            const uint32_t af3 = pack_h2(w[2 * mt + 1][2], w[2 * mt + 1][3]);
            #pragma unroll
            for (int nt = 0; nt < 4; ++nt)
                mma16(acc[mt][nt], af0, af1, af2, af3, b2[nt].x, b2[nt].y);
            if (do_den) {   // den from the ROUNDED fragments -> exact cancel
                const float2 q0 = h2f2(af0), q1 = h2f2(af1);
                const float2 q2 = h2f2(af2), q3 = h2f2(af3);
                dpT[2 * mt]     += (q0.x + q0.y) + (q2.x + q2.y);
                dpT[2 * mt + 1] += (q1.x + q1.y) + (q3.x + q3.y);
            }
        }
    };

    #pragma unroll 1
    for (int g = 0; g < NG3; ++g) {
        // ---- cuda-chunk buffers for this group ready ----
        CP_WAIT0();
        uint32_t bal[4];
        #pragma unroll
        for (int c = 0; c < 4; ++c) {
            const int v = (c == 0) ? ac4.x : (c == 1) ? ac4.y : (c == 2) ? ac4.z : ac4.w;
            bal[c] = __ballot_sync(0xffffffffu, v != 0);
        }
        if (lane < 4) sBal[g & 1][wid * 4 + lane] = bal[lane];
        __syncthreads();
        // stage next group's cuda chunk (qc = 3g+5) into the other h buffer
        if (g + 1 < NG3) {
            const int qc2 = 3 * g + 5;
            const uint32_t hdst = hdst0 + (uint32_t)(((g + 1) & 1) * 8192);
            ac4 = __ldg(csrc_base + qc2 * 4);
            CP_ASYNC16(hdst,      (const char*)(g_h + (size_t)qc2 * 2048) + t * 32);
            CP_ASYNC16(hdst + 16, (const char*)(g_h + (size_t)qc2 * 2048) + t * 32 + 16);
            CP_COMMIT();
        }

        // ---- 2 tensor chunks: q = 3g, 3g+1 (prefetch 3g+1 then 3g+3) ----
        tensor_chunk(3 * g,     3 * g + 1);
        tensor_chunk(3 * g + 1, 3 * g + 3);

        // ---- 1 cuda chunk (q = 3g+2) -> accC via packed FMA2 ----
        {
            const int qc = 3 * g + 2;
            const ull* hb = reinterpret_cast<const ull*>(sH + (g & 1) * 2048);
            uint32_t balw[4][4];
            #pragma unroll
            for (int k = 0; k < 4; ++k)
                #pragma unroll
                for (int c = 0; c < 4; ++c)
                    balw[k][c] = sBal[g & 1][(4 * mw + k) * 4 + c];
            float4 e4c[4], f4c[4];
            #pragma unroll
            for (int mq = 0; mq < 4; ++mq) {
                e4c[mq] = sE4[qc * 4 + mq];
                f4c[mq] = sF4[qc * 4 + mq];
            }
            #pragma unroll
            for (int j = 0; j < 16; ++j) {
                const int mq = j >> 2, cj = j & 3;
                const float E2j = (cj == 0) ? e4c[mq].x : (cj == 1) ? e4c[mq].y
                                  : (cj == 2) ? e4c[mq].z : e4c[mq].w;
                const float F2j = (cj == 0) ? f4c[mq].x : (cj == 1) ? f4c[mq].y
                                  : (cj == 2) ? f4c[mq].z : f4c[mq].w;
                ull h2[4];
                #pragma unroll
                for (int nt = 0; nt < 4; ++nt)
                    h2[nt] = hb[j * 64 + nw * 16 + 4 * nt + lc];
                const int sh = lr * 4 + mq;
                #pragma unroll
                for (int k = 0; k < 4; ++k) {
                    const float wv = fmaxf(e1[k] * E2j, f1[k] * F2j);
                    const float wg = ((balw[k][cj] >> sh) & 1u) ? wv : 0.f;
                    if (do_den) dpC[k] += wg;
                    ull wp; PACK2(wp, wg);
                    const int mt = k >> 1, rh = k & 1;
                    #pragma unroll
                    for (int nt = 0; nt < 4; ++nt)
                        FMA2(accC[mt][nt][rh], wp, h2[nt]);
                }
            }
        }
    }

    // ---- tail: tensor chunks 510, 511 ----
    tensor_chunk(510, 511);
    tensor_chunk(511, NQ);

    // ---- merge cuda accumulators into tensor accumulators ----
    #pragma unroll
    for (int mt = 0; mt < 2; ++mt)
        #pragma unroll
        for (int nt = 0; nt < 4; ++nt)
            #pragma unroll
            for (int rh = 0; rh < 2; ++rh) {
                float lo, hi;
                UNPACK2(lo, hi, accC[mt][nt][rh]);
                acc[mt][nt][rh * 2]     += lo;
                acc[mt][nt][rh * 2 + 1] += hi;
            }

    // ---- denominators ----
    if (do_den) {
        #pragma unroll
        for (int k = 0; k < 4; ++k) {
            float v = dpT[k];
            v += __shfl_xor_sync(0xffffffffu, v, 1);
            v += __shfl_xor_sync(0xffffffffu, v, 2);
            if (lc == 0) sDen[mw * 32 + 8 * k + lr] = v + dpC[k];
        }
    }
    __syncthreads();

    // ---- normalize + elu + store ----
    #pragma unroll
    for (int mt = 0; mt < 2; ++mt) {
        const int r0 = mw * 32 + mt * 16 + lr;
        const float inv0 = 1.f / sDen[r0];
        const float inv1 = 1.f / sDen[r0 + 8];
        #pragma unroll
        for (int nt = 0; nt < 4; ++nt) {
            const int col = nw * 32 + nt * 8 + lc * 2;
            float2 v0, v1;
            v0.x = elu_f(acc[mt][nt][0] * inv0);
            v0.y = elu_f(acc[mt][nt][1] * inv0);
            v1.x = elu_f(acc[mt][nt][2] * inv1);
            v1.y = elu_f(acc[mt][nt][3] * inv1);
            *reinterpret_cast<float2*>(out + (size_t)(i0 + r0) * FOUT + col)     = v0;
            *reinterpret_cast<float2*>(out + (size_t)(i0 + r0 + 8) * FOUT + col) = v1;
        }
    }
}

// ---------------------------------------------------------------------------
extern "C" void kernel_launch(void* const* d_in, const int* in_sizes, int n_in,
                              void* d_out, int out_size) {
    const float* X   = (const float*)d_in[0];   // 8192 x 512
    const int*   adj = (const int*)  d_in[1];   // 8192 x 8192
    const float* W   = (const float*)d_in[2];   // 512 x 128
    const float* a   = (const float*)d_in[3];   // 256 x 1
    float*       out = (float*)d_out;           // 8192 x 128

    cudaFuncSetAttribute(k_agg, cudaFuncAttributeMaxDynamicSharedMemorySize, 81920);

    k_gemm_hw<<<N / 64, 256>>>(X, W);
    k_scores<<<N, 128>>>(a);
    k_agg<<<N / 64, 256, 81920>>>(adj, out);
}

// round 11
// speedup vs baseline: 1.0761x; 1.0761x over previous
#include <cuda_runtime.h>
#include <cuda_fp16.h>
#include <cstdint>
#include <math.h>

typedef unsigned long long ull;

#define FMA2(acc, a, b) asm("fma.rn.f32x2 %0, %1, %2, %0;" : "+l"(acc) : "l"(a), "l"(b))
#define PACK2(d, s)     asm("mov.b64 %0, {%1, %1};" : "=l"(d) : "f"(s))
#define UNPACK2(lo, hi, s) asm("mov.b64 {%0, %1}, %2;" : "=f"(lo), "=f"(hi) : "l"(s))
#define CP_ASYNC16(dst, src) \
    asm volatile("cp.async.cg.shared.global [%0], [%1], 16;" :: "r"(dst), "l"(src) : "memory")
#define CP_COMMIT()  asm volatile("cp.async.commit_group;" ::: "memory")
#define CP_WAIT0()   asm volatile("cp.async.wait_group 0;" ::: "memory")
#define BAR_CUDA()   asm volatile("bar.sync 1, 256;" ::: "memory")

constexpr int N    = 8192;
constexpr int FIN  = 512;
constexpr int FOUT = 128;
constexpr int NQ   = 512;    // k16 chunks
constexpr int QT   = 288;    // tensor side: chunks [0, QT); cuda side: [QT, NQ)

__device__ float g_h[N * FOUT];
__device__ uint2 g_hTb[NQ * 16 * 4 * 8];     // fp16 B fragments of h^T (2MB, L2-resident)
__device__ float g_E1[N], g_F1[N], g_E2[N], g_F2[N];

__device__ __forceinline__ uint32_t smem_u32(const void* p) {
    return (uint32_t)__cvta_generic_to_shared(p);
}
__device__ __forceinline__ uint32_t pack_h2(float lo, float hi) {
    uint32_t r;
    asm("cvt.rn.f16x2.f32 %0, %1, %2;" : "=r"(r) : "f"(hi), "f"(lo));
    return r;
}
__device__ __forceinline__ float2 h2f2(uint32_t u) {
    __half2 h = *reinterpret_cast<const __half2*>(&u);
    return __half22float2(h);
}

// m16n8k16 fp16 warp MMA, fp32 accumulate
__device__ __forceinline__ void mma16(float* c, uint32_t a0, uint32_t a1, uint32_t a2,
                                      uint32_t a3, uint32_t b0, uint32_t b1) {
    asm volatile(
        "mma.sync.aligned.m16n8k16.row.col.f32.f16.f16.f32 "
        "{%0,%1,%2,%3}, {%4,%5,%6,%7}, {%8,%9}, {%0,%1,%2,%3};"
        : "+f"(c[0]), "+f"(c[1]), "+f"(c[2]), "+f"(c[3])
        : "r"(a0), "r"(a1), "r"(a2), "r"(a3), "r"(b0), "r"(b1));
}

__device__ __forceinline__ float elu_f(float v) { return v > 0.f ? v : expm1f(v); }

// ---------------------------------------------------------------------------
// Kernel A: h = X @ W (fp32 FFMA2), BM=64. Emits g_h and fp16 B-fragment hT.
// ---------------------------------------------------------------------------
__global__ void __launch_bounds__(256) k_gemm_hw(const float* __restrict__ X,
                                                 const float* __restrict__ W) {
    __shared__ float sX[64][32];
    __shared__ float sB[32][FOUT];
    const int t = threadIdx.x;
    const int tx = t & 31, ty = t >> 5;
    const int m0 = blockIdx.x * 64;
    const int xr = t >> 2, xc0 = (t & 3) * 8;
    const int wr = t >> 3, wc0 = (t & 7) * 16;

    ull acc[8][2] = {};
    for (int kc = 0; kc < FIN / 32; ++kc) {
        const int k0 = kc * 32;
        __syncthreads();
        {
            float4*       dx = reinterpret_cast<float4*>(&sX[xr][xc0]);
            const float4* sx = reinterpret_cast<const float4*>(X + (size_t)(m0 + xr) * FIN + k0 + xc0);
            dx[0] = sx[0]; dx[1] = sx[1];
            float4*       dw = reinterpret_cast<float4*>(&sB[wr][wc0]);
            const float4* sw = reinterpret_cast<const float4*>(W + (size_t)(k0 + wr) * FOUT + wc0);
            dw[0] = sw[0]; dw[1] = sw[1]; dw[2] = sw[2]; dw[3] = sw[3];
        }
        __syncthreads();
        #pragma unroll 8
        for (int kk = 0; kk < 32; ++kk) {
            ulonglong2 b2 = *reinterpret_cast<const ulonglong2*>(&sB[kk][tx << 2]);
            #pragma unroll
            for (int k = 0; k < 8; ++k) {
                ull ap; PACK2(ap, sX[ty + 8 * k][kk]);
                FMA2(acc[k][0], ap, b2.x);
                FMA2(acc[k][1], ap, b2.y);
            }
        }
    }
    __half* hTb = reinterpret_cast<__half*>(g_hTb);
    #pragma unroll
    for (int k = 0; k < 8; ++k) {
        const int r = m0 + ty + 8 * k;
        float4 o;
        UNPACK2(o.x, o.y, acc[k][0]);
        UNPACK2(o.z, o.w, acc[k][1]);
        reinterpret_cast<float4*>(g_h + (size_t)r * FOUT)[tx] = o;
        const int q  = r >> 4;
        const int lc = (r >> 2) & 3;
        const int p  = r & 3;
        const float v[4] = {o.x, o.y, o.z, o.w};
        #pragma unroll
        for (int c = 0; c < 4; ++c) {
            const int f = tx * 4 + c;
            const int idx = (((q * 16 + (f >> 3)) * 4 + lc) * 8 + (f & 7)) * 4 + p;
            hTb[idx] = __float2half_rn(v[c]);
        }
    }
}

// ---------------------------------------------------------------------------
// Kernel B: E/F exp vectors
// ---------------------------------------------------------------------------
__global__ void __launch_bounds__(128) k_scores(const float* __restrict__ a) {
    const int i = blockIdx.x;
    const int t = threadIdx.x;
    const float hv = g_h[(size_t)i * FOUT + t];
    float p1 = hv * __ldg(&a[t]);
    float p2 = hv * __ldg(&a[FOUT + t]);
    #pragma unroll
    for (int off = 16; off; off >>= 1) {
        p1 += __shfl_xor_sync(0xffffffffu, p1, off);
        p2 += __shfl_xor_sync(0xffffffffu, p2, off);
    }
    __shared__ float r1[4], r2[4];
    const int w = t >> 5;
    if ((t & 31) == 0) { r1[w] = p1; r2[w] = p2; }
    __syncthreads();
    if (t == 0) {
        const float s1 = r1[0] + r1[1] + r1[2] + r1[3];
        const float s2 = r2[0] + r2[1] + r2[2] + r2[3];
        g_E1[i] = __expf(s1);  g_F1[i] = __expf(0.2f * s1);
        g_E2[i] = __expf(s2);  g_F2[i] = __expf(0.2f * s2);
    }
}

// ---------------------------------------------------------------------------
// Kernel C: WARP-SPECIALIZED hybrid aggregation, 512 threads.
// Warps 0-7 (tensor): chunks [0,QT) via fp16 mma.sync (R6 path, own regs).
// Warps 8-15 (cuda):  chunks [QT,512) via packed FMA2 (R10 cuda body, own regs),
//                     h staged 8KB/chunk by cp.async, adj via ballots; synced
//                     among cuda warps only (bar.sync 1,256). Merge via smem.
// ---------------------------------------------------------------------------
__global__ void __launch_bounds__(512, 1) k_agg(const int* __restrict__ adj,
                                                float* __restrict__ out) {
    extern __shared__ float smem[];
    float* sEF   = smem;                    // 16384 f (64KB): E2 | F2
    float* sH    = smem + 2 * N;            // 4096 f (16KB): h chunk double buffer
    float* sAccC = smem + 2 * N + 4096;     // 8192 f (32KB): cuda-side accumulators
    __shared__ uint32_t sBal[2][32];
    __shared__ float sDen[64], sDenC[64];

    const int t = threadIdx.x;
    const int lane = t & 31, wid = t >> 5;
    const int i0 = blockIdx.x * 64;

    // stage E2/F2 tables (all 512 threads)
    {
        const float4* e4 = reinterpret_cast<const float4*>(g_E2);
        const float4* f4 = reinterpret_cast<const float4*>(g_F2);
        float4* s4 = reinterpret_cast<float4*>(sEF);
        for (int k = t; k < N / 4; k += 512) {
            s4[k]         = e4[k];
            s4[N / 4 + k] = f4[k];
        }
    }
    __syncthreads();   // (1)

    const float4* sE4 = reinterpret_cast<const float4*>(sEF);
    const float4* sF4 = reinterpret_cast<const float4*>(sEF + N);
    const int4* adj4 = reinterpret_cast<const int4*>(adj);

    if (wid < 8) {
        // ================= TENSOR SIDE =================
        const int mw = wid >> 2, nw = wid & 3;
        const int lr = lane >> 2, lc = lane & 3;
        const bool do_den = (wid == 1) || (wid == 6);

        float e1[4], f1[4];
        const int4* arow[4];
        #pragma unroll
        for (int k = 0; k < 4; ++k) {
            const int row = i0 + mw * 32 + lr + 8 * k;
            e1[k] = g_E1[row];
            f1[k] = g_F1[row];
            arow[k] = adj4 + (size_t)row * (N / 4) + lc;
        }

        int4 a4n[4];
        uint2 b2n[4];
        #pragma unroll
        for (int k = 0; k < 4; ++k) a4n[k] = __ldg(arow[k]);
        #pragma unroll
        for (int nt = 0; nt < 4; ++nt)
            b2n[nt] = __ldg(&g_hTb[((nw * 4 + nt) * 4 + lc) * 8 + lr]);

        float acc[2][4][4];
        #pragma unroll
        for (int mt = 0; mt < 2; ++mt)
            #pragma unroll
            for (int nt = 0; nt < 4; ++nt)
                #pragma unroll
                for (int r = 0; r < 4; ++r) acc[mt][nt][r] = 0.f;
        float dpT[4] = {0.f, 0.f, 0.f, 0.f};

        #pragma unroll 1
        for (int q = 0; q < QT; ++q) {
            int4 a4[4];
            uint2 b2[4];
            #pragma unroll
            for (int k = 0; k < 4; ++k) a4[k] = a4n[k];
            #pragma unroll
            for (int nt = 0; nt < 4; ++nt) b2[nt] = b2n[nt];
            if (q + 1 < QT) {
                #pragma unroll
                for (int k = 0; k < 4; ++k) a4n[k] = __ldg(arow[k] + (q + 1) * 4);
                #pragma unroll
                for (int nt = 0; nt < 4; ++nt)
                    b2n[nt] = __ldg(&g_hTb[(((q + 1) * 16 + nw * 4 + nt) * 4 + lc) * 8 + lr]);
            }
            const float4 e4 = sE4[q * 4 + lc];
            const float4 f4 = sF4[q * 4 + lc];

            float w[4][4];
            #pragma unroll
            for (int k = 0; k < 4; ++k) {
                const float ek = e1[k], fk = f1[k];
                w[k][0] = a4[k].x ? fmaxf(ek * e4.x, fk * f4.x) : 0.f;
                w[k][1] = a4[k].y ? fmaxf(ek * e4.y, fk * f4.y) : 0.f;
                w[k][2] = a4[k].z ? fmaxf(ek * e4.z, fk * f4.z) : 0.f;
                w[k][3] = a4[k].w ? fmaxf(ek * e4.w, fk * f4.w) : 0.f;
            }
            #pragma unroll
            for (int mt = 0; mt < 2; ++mt) {
                const uint32_t af0 = pack_h2(w[2 * mt][0],     w[2 * mt][1]);
                const uint32_t af1 = pack_h2(w[2 * mt + 1][0], w[2 * mt + 1][1]);
                const uint32_t af2 = pack_h2(w[2 * mt][2],     w[2 * mt][3]);
                const uint32_t af3 = pack_h2(w[2 * mt + 1][2], w[2 * mt + 1][3]);
                #pragma unroll
                for (int nt = 0; nt < 4; ++nt)
                    mma16(acc[mt][nt], af0, af1, af2, af3, b2[nt].x, b2[nt].y);
                if (do_den) {   // den from ROUNDED fragments -> exact cancel
                    const float2 q0 = h2f2(af0), q1 = h2f2(af1);
                    const float2 q2 = h2f2(af2), q3 = h2f2(af3);
                    dpT[2 * mt]     += (q0.x + q0.y) + (q2.x + q2.y);
                    dpT[2 * mt + 1] += (q1.x + q1.y) + (q3.x + q3.y);
                }
            }
        }

        if (do_den) {
            #pragma unroll
            for (int k = 0; k < 4; ++k) {
                float v = dpT[k];
                v += __shfl_xor_sync(0xffffffffu, v, 1);
                v += __shfl_xor_sync(0xffffffffu, v, 2);
                if (lc == 0) sDen[mw * 32 + 8 * k + lr] = v;
            }
        }

        __syncthreads();   // (2) join cuda side

        // merge cuda accumulators (cuda thread u==t wrote sAccC[t])
        {
            const float* mc = sAccC + t * 32;
            #pragma unroll
            for (int mt = 0; mt < 2; ++mt)
                #pragma unroll
                for (int nt = 0; nt < 4; ++nt)
                    #pragma unroll
                    for (int r = 0; r < 4; ++r)
                        acc[mt][nt][r] += mc[mt * 16 + nt * 4 + r];
        }

        // normalize + elu + store
        #pragma unroll
        for (int mt = 0; mt < 2; ++mt) {
            const int r0 = mw * 32 + mt * 16 + lr;
            const float inv0 = 1.f / (sDen[r0]     + sDenC[r0]);
            const float inv1 = 1.f / (sDen[r0 + 8] + sDenC[r0 + 8]);
            #pragma unroll
            for (int nt = 0; nt < 4; ++nt) {
                const int col = nw * 32 + nt * 8 + lc * 2;
                float2 v0, v1;
                v0.x = elu_f(acc[mt][nt][0] * inv0);
                v0.y = elu_f(acc[mt][nt][1] * inv0);
                v1.x = elu_f(acc[mt][nt][2] * inv1);
                v1.y = elu_f(acc[mt][nt][3] * inv1);
                *reinterpret_cast<float2*>(out + (size_t)(i0 + r0) * FOUT + col)     = v0;
                *reinterpret_cast<float2*>(out + (size_t)(i0 + r0 + 8) * FOUT + col) = v1;
            }
        }
    } else {
        // ================= CUDA SIDE =================
        const int u = t - 256;
        const int cw = wid - 8;
        const int mw = cw >> 2, nw = cw & 3;
        const int lr = lane >> 2, lc = lane & 3;
        const bool do_den = (cw == 1) || (cw == 6);

        float e1[4], f1[4];
        #pragma unroll
        for (int k = 0; k < 4; ++k) {
            const int row = i0 + mw * 32 + lr + 8 * k;
            e1[k] = g_E1[row];
            f1[k] = g_F1[row];
        }

        const int crow = u >> 2, cseg = u & 3;
        const int4* csrc = adj4 + (size_t)(i0 + crow) * (N / 4) + cseg;
        const uint32_t hdst0 = smem_u32(sH) + (uint32_t)u * 32;

        // prologue: stage chunk QT
        int4 ac4 = __ldg(csrc + QT * 4);
        {
            const uint32_t hd = hdst0 + (uint32_t)((QT & 1) * 8192);
            const char* src = (const char*)(g_h + (size_t)QT * 2048) + u * 32;
            CP_ASYNC16(hd, src);
            CP_ASYNC16(hd + 16, src + 16);
            CP_COMMIT();
        }

        ull accC[2][4][2] = {};
        float dpC[4] = {0.f, 0.f, 0.f, 0.f};

        #pragma unroll 1
        for (int q = QT; q < NQ; ++q) {
            CP_WAIT0();
            uint32_t bal[4];
            #pragma unroll
            for (int c = 0; c < 4; ++c) {
                const int v = (c == 0) ? ac4.x : (c == 1) ? ac4.y : (c == 2) ? ac4.z : ac4.w;
                bal[c] = __ballot_sync(0xffffffffu, v != 0);
            }
            if (lane < 4) sBal[q & 1][cw * 4 + lane] = bal[lane];
            BAR_CUDA();
            // prefetch chunk q+1
            if (q + 1 < NQ) {
                ac4 = __ldg(csrc + (q + 1) * 4);
                const uint32_t hd = hdst0 + (uint32_t)(((q + 1) & 1) * 8192);
                const char* src = (const char*)(g_h + (size_t)(q + 1) * 2048) + u * 32;
                CP_ASYNC16(hd, src);
                CP_ASYNC16(hd + 16, src + 16);
                CP_COMMIT();
            }
            // compute chunk q
            const ull* hb = reinterpret_cast<const ull*>(sH + (q & 1) * 2048);
            uint32_t balw[4][4];
            #pragma unroll
            for (int k = 0; k < 4; ++k)
                #pragma unroll
                for (int c = 0; c < 4; ++c)
                    balw[k][c] = sBal[q & 1][(4 * mw + k) * 4 + c];
            float4 e4c[4], f4c[4];
            #pragma unroll
            for (int mq = 0; mq < 4; ++mq) {
                e4c[mq] = sE4[q * 4 + mq];
                f4c[mq] = sF4[q * 4 + mq];
            }
            #pragma unroll
            for (int j = 0; j < 16; ++j) {
                const int mq = j >> 2, cj = j & 3;
                const float E2j = (cj == 0) ? e4c[mq].x : (cj == 1) ? e4c[mq].y
                                  : (cj == 2) ? e4c[mq].z : e4c[mq].w;
                const float F2j = (cj == 0) ? f4c[mq].x : (cj == 1) ? f4c[mq].y
                                  : (cj == 2) ? f4c[mq].z : f4c[mq].w;
                ull h2[4];
                #pragma unroll
                for (int nt = 0; nt < 4; ++nt)
                    h2[nt] = hb[j * 64 + nw * 16 + 4 * nt + lc];
                const int sh = lr * 4 + mq;
                #pragma unroll
                for (int k = 0; k < 4; ++k) {
                    const float wv = fmaxf(e1[k] * E2j, f1[k] * F2j);
                    const float wg = ((balw[k][cj] >> sh) & 1u) ? wv : 0.f;
                    if (do_den) dpC[k] += wg;
                    ull wp; PACK2(wp, wg);
                    const int mt = k >> 1, rh = k & 1;
                    #pragma unroll
                    for (int nt = 0; nt < 4; ++nt)
                        FMA2(accC[mt][nt][rh], wp, h2[nt]);
                }
            }
        }

        // export accumulators + den
        {
            float* mc = sAccC + u * 32;
            #pragma unroll
            for (int mt = 0; mt < 2; ++mt)
                #pragma unroll
                for (int nt = 0; nt < 4; ++nt)
                    #pragma unroll
                    for (int rh = 0; rh < 2; ++rh) {
                        float lo, hi;
                        UNPACK2(lo, hi, accC[mt][nt][rh]);
                        mc[mt * 16 + nt * 4 + rh * 2]     = lo;
                        mc[mt * 16 + nt * 4 + rh * 2 + 1] = hi;
                    }
        }
        if (do_den && lc == 0) {
            #pragma unroll
            for (int k = 0; k < 4; ++k)
                sDenC[mw * 32 + 8 * k + lr] = dpC[k];
        }
        __syncthreads();   // (2) join tensor side
    }
}

// ---------------------------------------------------------------------------
extern "C" void kernel_launch(void* const* d_in, const int* in_sizes, int n_in,
                              void* d_out, int out_size) {
    const float* X   = (const float*)d_in[0];   // 8192 x 512
    const int*   adj = (const int*)  d_in[1];   // 8192 x 8192
    const float* W   = (const float*)d_in[2];   // 512 x 128
    const float* a   = (const float*)d_in[3];   // 256 x 1
    float*       out = (float*)d_out;           // 8192 x 128

    cudaFuncSetAttribute(k_agg, cudaFuncAttributeMaxDynamicSharedMemorySize, 115712);

    k_gemm_hw<<<N / 64, 256>>>(X, W);
    k_scores<<<N, 128>>>(a);
    k_agg<<<N / 64, 512, 115712>>>(adj, out);
}

// round 12
// speedup vs baseline: 2.2139x; 2.0573x over previous
#include <cuda_runtime.h>
#include <cuda_fp16.h>
#include <cstdint>
#include <math.h>

typedef unsigned long long ull;

#define FMA2(acc, a, b) asm("fma.rn.f32x2 %0, %1, %2, %0;" : "+l"(acc) : "l"(a), "l"(b))
#define PACK2(d, s)     asm("mov.b64 %0, {%1, %1};" : "=l"(d) : "f"(s))
#define UNPACK2(lo, hi, s) asm("mov.b64 {%0, %1}, %2;" : "=f"(lo), "=f"(hi) : "l"(s))

constexpr int N    = 8192;
constexpr int FIN  = 512;
constexpr int FOUT = 128;
constexpr int NQ   = 512;    // k16 chunks; group0: [0,256), group1: [256,512)

__device__ float g_h[N * FOUT];
__device__ uint2 g_hTb[NQ * 16 * 4 * 8];     // fp16 B fragments of h^T (2MB, L2-resident)
__device__ float g_E1[N], g_F1[N], g_E2[N], g_F2[N];

__device__ __forceinline__ uint32_t pack_h2(float lo, float hi) {
    uint32_t r;
    asm("cvt.rn.f16x2.f32 %0, %1, %2;" : "=r"(r) : "f"(hi), "f"(lo));
    return r;
}
__device__ __forceinline__ float2 h2f2(uint32_t u) {
    __half2 h = *reinterpret_cast<const __half2*>(&u);
    return __half22float2(h);
}

// m16n8k16 fp16 warp MMA, fp32 accumulate
__device__ __forceinline__ void mma16(float* c, uint32_t a0, uint32_t a1, uint32_t a2,
                                      uint32_t a3, uint32_t b0, uint32_t b1) {
    asm volatile(
        "mma.sync.aligned.m16n8k16.row.col.f32.f16.f16.f32 "
        "{%0,%1,%2,%3}, {%4,%5,%6,%7}, {%8,%9}, {%0,%1,%2,%3};"
        : "+f"(c[0]), "+f"(c[1]), "+f"(c[2]), "+f"(c[3])
        : "r"(a0), "r"(a1), "r"(a2), "r"(a3), "r"(b0), "r"(b1));
}

__device__ __forceinline__ float elu_f(float v) { return v > 0.f ? v : expm1f(v); }

// ---------------------------------------------------------------------------
// Kernel A: h = X @ W (fp32 FFMA2), BM=64. Emits g_h and fp16 B-fragment hT.
// ---------------------------------------------------------------------------
__global__ void __launch_bounds__(256) k_gemm_hw(const float* __restrict__ X,
                                                 const float* __restrict__ W) {
    __shared__ float sX[64][32];
    __shared__ float sB[32][FOUT];
    const int t = threadIdx.x;
    const int tx = t & 31, ty = t >> 5;
    const int m0 = blockIdx.x * 64;
    const int xr = t >> 2, xc0 = (t & 3) * 8;
    const int wr = t >> 3, wc0 = (t & 7) * 16;

    ull acc[8][2] = {};
    for (int kc = 0; kc < FIN / 32; ++kc) {
        const int k0 = kc * 32;
        __syncthreads();
        {
            float4*       dx = reinterpret_cast<float4*>(&sX[xr][xc0]);
            const float4* sx = reinterpret_cast<const float4*>(X + (size_t)(m0 + xr) * FIN + k0 + xc0);
            dx[0] = sx[0]; dx[1] = sx[1];
            float4*       dw = reinterpret_cast<float4*>(&sB[wr][wc0]);
            const float4* sw = reinterpret_cast<const float4*>(W + (size_t)(k0 + wr) * FOUT + wc0);
            dw[0] = sw[0]; dw[1] = sw[1]; dw[2] = sw[2]; dw[3] = sw[3];
        }
        __syncthreads();
        #pragma unroll 8
        for (int kk = 0; kk < 32; ++kk) {
            ulonglong2 b2 = *reinterpret_cast<const ulonglong2*>(&sB[kk][tx << 2]);
            #pragma unroll
            for (int k = 0; k < 8; ++k) {
                ull ap; PACK2(ap, sX[ty + 8 * k][kk]);
                FMA2(acc[k][0], ap, b2.x);
                FMA2(acc[k][1], ap, b2.y);
            }
        }
    }
    __half* hTb = reinterpret_cast<__half*>(g_hTb);
    #pragma unroll
    for (int k = 0; k < 8; ++k) {
        const int r = m0 + ty + 8 * k;
        float4 o;
        UNPACK2(o.x, o.y, acc[k][0]);
        UNPACK2(o.z, o.w, acc[k][1]);
        reinterpret_cast<float4*>(g_h + (size_t)r * FOUT)[tx] = o;
        const int q  = r >> 4;
        const int lc = (r >> 2) & 3;
        const int p  = r & 3;
        const float v[4] = {o.x, o.y, o.z, o.w};
        #pragma unroll
        for (int c = 0; c < 4; ++c) {
            const int f = tx * 4 + c;
            const int idx = (((q * 16 + (f >> 3)) * 4 + lc) * 8 + (f & 7)) * 4 + p;
            hTb[idx] = __float2half_rn(v[c]);
        }
    }
}

// ---------------------------------------------------------------------------
// Kernel B: E/F exp vectors
// ---------------------------------------------------------------------------
__global__ void __launch_bounds__(128) k_scores(const float* __restrict__ a) {
    const int i = blockIdx.x;
    const int t = threadIdx.x;
    const float hv = g_h[(size_t)i * FOUT + t];
    float p1 = hv * __ldg(&a[t]);
    float p2 = hv * __ldg(&a[FOUT + t]);
    #pragma unroll
    for (int off = 16; off; off >>= 1) {
        p1 += __shfl_xor_sync(0xffffffffu, p1, off);
        p2 += __shfl_xor_sync(0xffffffffu, p2, off);
    }
    __shared__ float r1[4], r2[4];
    const int w = t >> 5;
    if ((t & 31) == 0) { r1[w] = p1; r2[w] = p2; }
    __syncthreads();
    if (t == 0) {
        const float s1 = r1[0] + r1[1] + r1[2] + r1[3];
        const float s2 = r2[0] + r2[1] + r2[2] + r2[3];
        g_E1[i] = __expf(s1);  g_F1[i] = __expf(0.2f * s1);
        g_E2[i] = __expf(s2);  g_F2[i] = __expf(0.2f * s2);
    }
}

// ---------------------------------------------------------------------------
// Kernel C: fp16 warp-MMA aggregation, 16 warps (512 thr), j-split in CTA.
// Warp-group 0 (wid 0-7): chunks [0,256). Warp-group 1 (wid 8-15): [256,512).
// 4 warps/SMSP x 8 independent HMMAs = 32 in flight per SMSP (latency test).
// No mainloop syncs; merge group-1 accumulators + dens via smem at the end.
// den from ROUNDED fp16 fragments on wid 1,6,9,14 -> exact softmax cancel.
// ---------------------------------------------------------------------------
__global__ void __launch_bounds__(512, 1) k_agg(const int* __restrict__ adj,
                                                float* __restrict__ out) {
    extern __shared__ float smem[];
    float* sEF    = smem;                   // 16384 f (64KB): E2 | F2
    float* sMerge = smem + 2 * N;           // 8192 f (32KB): group-1 accumulators
    __shared__ float sDen0[64], sDen1[64];

    const int t = threadIdx.x;
    const int lane = t & 31, wid = t >> 5;
    const int wg = wid >> 3;                // 0 or 1 (chunk-range group)
    const int w8 = wid & 7;
    const int mw = w8 >> 2, nw = w8 & 3;
    const int lr = lane >> 2, lc = lane & 3;
    const int i0 = blockIdx.x * 64;
    const bool do_den = (w8 == 1) || (w8 == 6);   // wid 1,6 (g0); 9,14 (g1)
    const int q0 = wg * 256, q1 = q0 + 256;

    // stage E2/F2 tables
    {
        const float4* e4 = reinterpret_cast<const float4*>(g_E2);
        const float4* f4 = reinterpret_cast<const float4*>(g_F2);
        float4* s4 = reinterpret_cast<float4*>(sEF);
        for (int k = t; k < N / 4; k += 512) {
            s4[k]         = e4[k];
            s4[N / 4 + k] = f4[k];
        }
    }
    __syncthreads();

    const float4* sE4 = reinterpret_cast<const float4*>(sEF);
    const float4* sF4 = reinterpret_cast<const float4*>(sEF + N);
    const int4* adj4 = reinterpret_cast<const int4*>(adj);

    float e1[4], f1[4];
    const int4* arow[4];
    #pragma unroll
    for (int k = 0; k < 4; ++k) {
        const int row = i0 + mw * 32 + lr + 8 * k;
        e1[k] = g_E1[row];
        f1[k] = g_F1[row];
        arow[k] = adj4 + (size_t)row * (N / 4) + lc;
    }

    // depth-1 register prefetch (R4-style; no ring)
    int4 a4n[4];
    uint2 b2n[4];
    #pragma unroll
    for (int k = 0; k < 4; ++k) a4n[k] = __ldg(arow[k] + q0 * 4);
    #pragma unroll
    for (int nt = 0; nt < 4; ++nt)
        b2n[nt] = __ldg(&g_hTb[((q0 * 16 + nw * 4 + nt) * 4 + lc) * 8 + lr]);

    float acc[2][4][4];
    #pragma unroll
    for (int mt = 0; mt < 2; ++mt)
        #pragma unroll
        for (int nt = 0; nt < 4; ++nt)
            #pragma unroll
            for (int r = 0; r < 4; ++r) acc[mt][nt][r] = 0.f;
    float dpT[4] = {0.f, 0.f, 0.f, 0.f};

    #pragma unroll 1
    for (int q = q0; q < q1; ++q) {
        int4 a4[4];
        uint2 b2[4];
        #pragma unroll
        for (int k = 0; k < 4; ++k) a4[k] = a4n[k];
        #pragma unroll
        for (int nt = 0; nt < 4; ++nt) b2[nt] = b2n[nt];
        if (q + 1 < q1) {
            #pragma unroll
            for (int k = 0; k < 4; ++k) a4n[k] = __ldg(arow[k] + (q + 1) * 4);
            #pragma unroll
            for (int nt = 0; nt < 4; ++nt)
                b2n[nt] = __ldg(&g_hTb[(((q + 1) * 16 + nw * 4 + nt) * 4 + lc) * 8 + lr]);
        }
        const float4 e4 = sE4[q * 4 + lc];
        const float4 f4 = sF4[q * 4 + lc];

        float w[4][4];
        #pragma unroll
        for (int k = 0; k < 4; ++k) {
            const float ek = e1[k], fk = f1[k];
            w[k][0] = a4[k].x ? fmaxf(ek * e4.x, fk * f4.x) : 0.f;
            w[k][1] = a4[k].y ? fmaxf(ek * e4.y, fk * f4.y) : 0.f;
            w[k][2] = a4[k].z ? fmaxf(ek * e4.z, fk * f4.z) : 0.f;
            w[k][3] = a4[k].w ? fmaxf(ek * e4.w, fk * f4.w) : 0.f;
        }
        #pragma unroll
        for (int mt = 0; mt < 2; ++mt) {
            const uint32_t af0 = pack_h2(w[2 * mt][0],     w[2 * mt][1]);
            const uint32_t af1 = pack_h2(w[2 * mt + 1][0], w[2 * mt + 1][1]);
            const uint32_t af2 = pack_h2(w[2 * mt][2],     w[2 * mt][3]);
            const uint32_t af3 = pack_h2(w[2 * mt + 1][2], w[2 * mt + 1][3]);
            #pragma unroll
            for (int nt = 0; nt < 4; ++nt)
                mma16(acc[mt][nt], af0, af1, af2, af3, b2[nt].x, b2[nt].y);
            if (do_den) {   // den from ROUNDED fragments -> exact cancel
                const float2 d0 = h2f2(af0), d1 = h2f2(af1);
                const float2 d2 = h2f2(af2), d3 = h2f2(af3);
                dpT[2 * mt]     += (d0.x + d0.y) + (d2.x + d2.y);
                dpT[2 * mt + 1] += (d1.x + d1.y) + (d3.x + d3.y);
            }
        }
    }

    // per-group denominators
    if (do_den) {
        #pragma unroll
        for (int k = 0; k < 4; ++k) {
            float v = dpT[k];
            v += __shfl_xor_sync(0xffffffffu, v, 1);
            v += __shfl_xor_sync(0xffffffffu, v, 2);
            if (lc == 0) {
                if (wg == 0) sDen0[mw * 32 + 8 * k + lr] = v;
                else         sDen1[mw * 32 + 8 * k + lr] = v;
            }
        }
    }

    // group 1 exports accumulators
    if (wg == 1) {
        const int u = t - 256;
        float* mc = sMerge + u * 32;
        #pragma unroll
        for (int mt = 0; mt < 2; ++mt)
            #pragma unroll
            for (int nt = 0; nt < 4; ++nt)
                #pragma unroll
                for (int r = 0; r < 4; ++r)
                    mc[mt * 16 + nt * 4 + r] = acc[mt][nt][r];
    }
    __syncthreads();

    // group 0 merges, normalizes, stores
    if (wg == 0) {
        const float* mc = sMerge + t * 32;
        #pragma unroll
        for (int mt = 0; mt < 2; ++mt)
            #pragma unroll
            for (int nt = 0; nt < 4; ++nt)
                #pragma unroll
                for (int r = 0; r < 4; ++r)
                    acc[mt][nt][r] += mc[mt * 16 + nt * 4 + r];

        #pragma unroll
        for (int mt = 0; mt < 2; ++mt) {
            const int r0 = mw * 32 + mt * 16 + lr;
            const float inv0 = 1.f / (sDen0[r0]     + sDen1[r0]);
            const float inv1 = 1.f / (sDen0[r0 + 8] + sDen1[r0 + 8]);
            #pragma unroll
            for (int nt = 0; nt < 4; ++nt) {
                const int col = nw * 32 + nt * 8 + lc * 2;
                float2 v0, v1;
                v0.x = elu_f(acc[mt][nt][0] * inv0);
                v0.y = elu_f(acc[mt][nt][1] * inv0);
                v1.x = elu_f(acc[mt][nt][2] * inv1);
                v1.y = elu_f(acc[mt][nt][3] * inv1);
                *reinterpret_cast<float2*>(out + (size_t)(i0 + r0) * FOUT + col)     = v0;
                *reinterpret_cast<float2*>(out + (size_t)(i0 + r0 + 8) * FOUT + col) = v1;
            }
        }
    }
}

// ---------------------------------------------------------------------------
extern "C" void kernel_launch(void* const* d_in, const int* in_sizes, int n_in,
                              void* d_out, int out_size) {
    const float* X   = (const float*)d_in[0];   // 8192 x 512
    const int*   adj = (const int*)  d_in[1];   // 8192 x 8192
    const float* W   = (const float*)d_in[2];   // 512 x 128
    const float* a   = (const float*)d_in[3];   // 256 x 1
    float*       out = (float*)d_out;           // 8192 x 128

    cudaFuncSetAttribute(k_agg, cudaFuncAttributeMaxDynamicSharedMemorySize, 98304);

    k_gemm_hw<<<N / 64, 256>>>(X, W);
    k_scores<<<N, 128>>>(a);
    k_agg<<<N / 64, 512, 98304>>>(adj, out);
}